// round 2
// baseline (speedup 1.0000x reference)
#include <cuda_runtime.h>
#include <math.h>

#define N_TOT   131072
#define D       512
#define DA      256
#define NH      4
#define NC      53
#define BAG     16
#define NBAGS   8192

// scratch (device globals — no allocation allowed)
__device__ float g_w[N_TOT];        // per-sentence attention weight (head-mean alpha)
__device__ float g_WcT[NC * D];     // Wc transposed to (C, D) for coalesced dots

// ---------------------------------------------------------------------------
// Kernel 0: transpose Wc (D,C) -> (C,D)
// ---------------------------------------------------------------------------
__global__ void transpose_wc_kernel(const float* __restrict__ Wc) {
    int i = blockIdx.x * blockDim.x + threadIdx.x;
    if (i < D * NC) {
        int d = i / NC;
        int c = i - d * NC;
        g_WcT[c * D + d] = Wc[i];
    }
}

// ---------------------------------------------------------------------------
// Kernel 1: fused  s = tanh(x@W1)@W2  -> per-bag softmax -> head mean -> g_w
// Block: 256 threads, tile M=64 rows (4 bags) x N=256 cols (full D_ATT), K=512.
// Thread microtile: 8x8. warp = row-group (8 rows? no: 8 warps x 8 rows = 64),
// lanes span all 256 cols -> per-row reduction is a warp shuffle reduce.
// ---------------------------------------------------------------------------
__global__ __launch_bounds__(256) void scores_kernel(
    const float* __restrict__ x,
    const float* __restrict__ W1,
    const float* __restrict__ W2)
{
    __shared__ float As[16][64];        // A chunk, transposed: As[k][m]
    __shared__ float Bs[16][256];       // W1 chunk: Bs[k][n]
    __shared__ float W2s[DA * NH];      // 4 KB
    __shared__ float sS[64][NH];        // scores then alpha, per row per head

    const int tid  = threadIdx.x;
    const int warp = tid >> 5;          // 0..7  -> rows warp*8 .. warp*8+7
    const int lane = tid & 31;          // 0..31 -> cols lane*8 .. lane*8+7
    const int rowBase = blockIdx.x * 64;

    // stage W2 (256x4)
    for (int i = tid; i < DA * NH; i += 256) W2s[i] = W2[i];

    float acc[8][8];
#pragma unroll
    for (int i = 0; i < 8; i++)
#pragma unroll
        for (int j = 0; j < 8; j++) acc[i][j] = 0.0f;

    // A-load mapping: thread -> (row = tid/4, k-quad = (tid%4)*4)
    const int la_r  = tid >> 2;
    const int la_kq = (tid & 3) << 2;

    for (int k0 = 0; k0 < D; k0 += 16) {
        // load A chunk: 64 rows x 16 k (float4 along k, store transposed)
        {
            float4 v = *(const float4*)&x[(size_t)(rowBase + la_r) * D + k0 + la_kq];
            As[la_kq + 0][la_r] = v.x;
            As[la_kq + 1][la_r] = v.y;
            As[la_kq + 2][la_r] = v.z;
            As[la_kq + 3][la_r] = v.w;
        }
        // load B chunk: 16 k x 256 cols (1024 float4, 4 per thread, coalesced)
#pragma unroll
        for (int i = 0; i < 4; i++) {
            int f  = tid + i * 256;       // float4 index 0..1023
            int k  = f >> 6;              // /64
            int c4 = (f & 63) << 2;
            *(float4*)&Bs[k][c4] = *(const float4*)&W1[(size_t)(k0 + k) * DA + c4];
        }
        __syncthreads();

#pragma unroll
        for (int k = 0; k < 16; k++) {
            float a[8], b[8];
            *(float4*)(a)     = *(const float4*)&As[k][warp * 8];
            *(float4*)(a + 4) = *(const float4*)&As[k][warp * 8 + 4];
            *(float4*)(b)     = *(const float4*)&Bs[k][lane * 8];
            *(float4*)(b + 4) = *(const float4*)&Bs[k][lane * 8 + 4];
#pragma unroll
            for (int i = 0; i < 8; i++)
#pragma unroll
                for (int j = 0; j < 8; j++)
                    acc[i][j] = fmaf(a[i], b[j], acc[i][j]);
        }
        __syncthreads();
    }

    // epilogue: tanh, multiply by W2, per-row-per-head partials
    float p[8][NH];
#pragma unroll
    for (int i = 0; i < 8; i++)
#pragma unroll
        for (int h = 0; h < NH; h++) p[i][h] = 0.0f;

#pragma unroll
    for (int i = 0; i < 8; i++) {
#pragma unroll
        for (int j = 0; j < 8; j++) {
            float t = tanhf(acc[i][j]);
            int col = lane * 8 + j;
#pragma unroll
            for (int h = 0; h < NH; h++)
                p[i][h] = fmaf(t, W2s[col * NH + h], p[i][h]);
        }
    }

    // warp-reduce partials over the 32 lanes (each warp owns 8 full rows)
#pragma unroll
    for (int i = 0; i < 8; i++) {
#pragma unroll
        for (int h = 0; h < NH; h++) {
            float v = p[i][h];
            v += __shfl_xor_sync(0xffffffffu, v, 16);
            v += __shfl_xor_sync(0xffffffffu, v, 8);
            v += __shfl_xor_sync(0xffffffffu, v, 4);
            v += __shfl_xor_sync(0xffffffffu, v, 2);
            v += __shfl_xor_sync(0xffffffffu, v, 1);
            if (lane == 0) sS[warp * 8 + i][h] = v;
        }
    }
    __syncthreads();

    // per-bag per-head softmax: 4 bags x 4 heads = 16 workers
    if (tid < 16) {
        int bag = tid >> 2;
        int h   = tid & 3;
        int r0  = bag * BAG;
        float mx = -INFINITY;
#pragma unroll
        for (int r = 0; r < BAG; r++) mx = fmaxf(mx, sS[r0 + r][h]);
        float den = 0.0f;
#pragma unroll
        for (int r = 0; r < BAG; r++) {
            float e = expf(sS[r0 + r][h] - mx);
            sS[r0 + r][h] = e;
            den += e;
        }
        float inv = 1.0f / den;
#pragma unroll
        for (int r = 0; r < BAG; r++) sS[r0 + r][h] *= inv;
    }
    __syncthreads();

    // head-mean -> per-sentence weight
    if (tid < 64) {
        float w = 0.25f * (sS[tid][0] + sS[tid][1] + sS[tid][2] + sS[tid][3]);
        g_w[rowBase + tid] = w;
    }
}

// ---------------------------------------------------------------------------
// Kernel 2: per bag: bag_repr = sum_r w_r * x_r ; logits = bag_repr@Wc + bc
// One block (256 threads) per bag.
// ---------------------------------------------------------------------------
__global__ __launch_bounds__(256) void bag_kernel(
    const float* __restrict__ x,
    const float* __restrict__ bc,
    float* __restrict__ out)
{
    __shared__ float rep[D];
    __shared__ float ws[BAG];

    const int b   = blockIdx.x;
    const int tid = threadIdx.x;

    if (tid < BAG) ws[tid] = g_w[b * BAG + tid];
    __syncthreads();

    const float* xb = x + (size_t)b * BAG * D;
    float r0 = 0.0f, r1 = 0.0f;
#pragma unroll
    for (int r = 0; r < BAG; r++) {
        float w = ws[r];
        r0 = fmaf(w, xb[r * D + tid],       r0);
        r1 = fmaf(w, xb[r * D + tid + 256], r1);
    }
    rep[tid]       = r0;
    rep[tid + 256] = r1;
    __syncthreads();

    const int warp = tid >> 5;
    const int lane = tid & 31;
    for (int c = warp; c < NC; c += 8) {
        const float* wc = &g_WcT[c * D];
        float s = 0.0f;
        // 128 float4 per row, 4 per lane
#pragma unroll
        for (int q = 0; q < 4; q++) {
            int d4 = lane + q * 32;
            float4 rv = *(const float4*)&rep[d4 * 4];
            float4 wv = *(const float4*)&wc[d4 * 4];
            s = fmaf(rv.x, wv.x, s);
            s = fmaf(rv.y, wv.y, s);
            s = fmaf(rv.z, wv.z, s);
            s = fmaf(rv.w, wv.w, s);
        }
        s += __shfl_xor_sync(0xffffffffu, s, 16);
        s += __shfl_xor_sync(0xffffffffu, s, 8);
        s += __shfl_xor_sync(0xffffffffu, s, 4);
        s += __shfl_xor_sync(0xffffffffu, s, 2);
        s += __shfl_xor_sync(0xffffffffu, s, 1);
        if (lane == 0) out[b * NC + c] = s + bc[c];
    }
}

// ---------------------------------------------------------------------------
extern "C" void kernel_launch(void* const* d_in, const int* in_sizes, int n_in,
                              void* d_out, int out_size)
{
    const float* x  = (const float*)d_in[0];
    const float* W1 = (const float*)d_in[1];
    const float* W2 = (const float*)d_in[2];
    const float* Wc = (const float*)d_in[3];
    const float* bc = (const float*)d_in[4];
    float* out = (float*)d_out;

    transpose_wc_kernel<<<(D * NC + 255) / 256, 256>>>(Wc);
    scores_kernel<<<N_TOT / 64, 256>>>(x, W1, W2);
    bag_kernel<<<NBAGS, 256>>>(x, bc, out);
}

// round 5
// speedup vs baseline: 2.2472x; 2.2472x over previous
#include <cuda_runtime.h>
#include <cuda_bf16.h>
#include <cstdint>
#include <math.h>

#define N_TOT   131072
#define D       512
#define DA      256
#define NH      4
#define NC      53
#define BAG     16
#define NBAGS   8192

#define MT      64          // CTA rows (4 bags)
#define KCH     64          // K chunk
#define NCHUNK  (D / KCH)   // 8

// ---------------------------------------------------------------------------
// device scratch (allocation is forbidden)
// ---------------------------------------------------------------------------
__device__ float g_w[N_TOT];
__device__ float g_WcT[NC * D];
__device__ __align__(256) __nv_bfloat16 g_W1hT[DA * D];   // (n, k) k-contig
__device__ __align__(256) __nv_bfloat16 g_W1lT[DA * D];

// ---------------------------------------------------------------------------
// helpers
// ---------------------------------------------------------------------------
__device__ __forceinline__ uint32_t smem_u32(const void* p) {
    uint32_t a;
    asm("{ .reg .u64 t; cvta.to.shared.u64 t, %1; cvt.u32.u64 %0, t; }" : "=r"(a) : "l"(p));
    return a;
}
__device__ __forceinline__ uint32_t sw128(uint32_t o) { return o ^ ((o >> 3) & 0x70); }

#define CP_ASYNC16(dst, src) \
    asm volatile("cp.async.cg.shared.global [%0], [%1], 16;" :: "r"(dst), "l"(src) : "memory")
#define CP_COMMIT() asm volatile("cp.async.commit_group;" ::: "memory")
#define CP_WAIT1()  asm volatile("cp.async.wait_group 1;" ::: "memory")
#define CP_WAIT0()  asm volatile("cp.async.wait_group 0;" ::: "memory")

__device__ __forceinline__ void ldsm_x4(uint32_t& r0, uint32_t& r1, uint32_t& r2,
                                        uint32_t& r3, uint32_t addr) {
    asm volatile("ldmatrix.sync.aligned.m8n8.x4.shared.b16 {%0,%1,%2,%3}, [%4];"
                 : "=r"(r0), "=r"(r1), "=r"(r2), "=r"(r3) : "r"(addr));
}

__device__ __forceinline__ void mma_bf16(float* d, const uint32_t* a, const uint32_t* b) {
    asm volatile("mma.sync.aligned.m16n8k16.row.col.f32.bf16.bf16.f32 "
                 "{%0,%1,%2,%3}, {%4,%5,%6,%7}, {%8,%9}, {%0,%1,%2,%3};"
                 : "+f"(d[0]), "+f"(d[1]), "+f"(d[2]), "+f"(d[3])
                 : "r"(a[0]), "r"(a[1]), "r"(a[2]), "r"(a[3]), "r"(b[0]), "r"(b[1]));
}

__device__ __forceinline__ float ftanh(float v) {
    float e2 = __expf(2.0f * v);
    return 1.0f - __fdividef(2.0f, e2 + 1.0f);
}
__device__ __forceinline__ uint32_t pack_bf2(float a, float b) {
    __nv_bfloat162 h = __floats2bfloat162_rn(a, b);
    return *reinterpret_cast<uint32_t*>(&h);
}

// ---------------------------------------------------------------------------
// prep kernels
// ---------------------------------------------------------------------------
__global__ void transpose_wc_kernel(const float* __restrict__ Wc) {
    int i = blockIdx.x * blockDim.x + threadIdx.x;
    if (i < D * NC) {
        int d = i / NC, c = i - d * NC;
        g_WcT[c * D + d] = Wc[i];
    }
}
__global__ void convert_w1_kernel(const float* __restrict__ W1) {
    int i = blockIdx.x * blockDim.x + threadIdx.x;   // over D*DA, (k, n) layout in
    if (i < D * DA) {
        int k = i >> 8, n = i & 255;
        float v = W1[i];
        __nv_bfloat16 h = __float2bfloat16_rn(v);
        float lo = v - __bfloat162float(h);
        g_W1hT[n * D + k] = h;
        g_W1lT[n * D + k] = __float2bfloat16_rn(lo);
    }
}

// ---------------------------------------------------------------------------
// scores kernel: bf16-split mma.sync GEMM (64x256xK) + tanh/W2 + bag softmax
// smem: [0,4K) W2 float4[256]; [4K,8K) sRed4 [4][64][4]; stages at 8K:
//   per stage (80K): Ahi 8K | Alo 8K | Bhi 32K | Blo 32K
// ---------------------------------------------------------------------------
#define SO_W2    0
#define SO_RED   4096
#define SO_STG   8192
#define STG_SZ   81920
#define SOF_AL   8192
#define SOF_BH   16384
#define SOF_BL   49152
#define SMEM_SZ  (SO_STG + 2 * STG_SZ)   // 172032

__global__ void __launch_bounds__(256, 1) scores_mma_kernel(
    const float* __restrict__ x,
    const float* __restrict__ W2)
{
    extern __shared__ char smem[];
    const uint32_t sb = smem_u32(smem);
    const int tid  = threadIdx.x;
    const int warp = tid >> 5;
    const int lane = tid & 31;
    const int wm = warp & 1;        // 0..1 : 32-row group
    const int wn = warp >> 1;       // 0..3 : 64-col group
    const size_t rowBase = (size_t)blockIdx.x * MT;
    const float* xrow = x + rowBase * D;

    float4* W2s = (float4*)(smem + SO_W2);
    for (int i = tid; i < DA; i += 256) W2s[i] = ((const float4*)W2)[i];

    float acc[2][8][4];
#pragma unroll
    for (int mt = 0; mt < 2; mt++)
#pragma unroll
        for (int nt = 0; nt < 8; nt++)
#pragma unroll
            for (int q = 0; q < 4; q++) acc[mt][nt][q] = 0.0f;

    // ---- pipeline helpers (inlined manually) ----
    float4 av[4];

    // prologue: B0 cp.async, A0 ldg+convert+STS
    {
#pragma unroll
        for (int i = 0; i < 8; i++) {
            int f = tid + i * 256;
            int n = f >> 3, k8 = f & 7;
            uint32_t d = sw128((uint32_t)(n * 128 + k8 * 16));
            CP_ASYNC16(sb + SO_STG + SOF_BH + d, g_W1hT + n * D + k8 * 8);
            CP_ASYNC16(sb + SO_STG + SOF_BL + d, g_W1lT + n * D + k8 * 8);
        }
        CP_COMMIT();
#pragma unroll
        for (int i = 0; i < 4; i++) {
            int f = tid + i * 256;
            int r = f >> 4, k4 = (f & 15) << 2;
            av[i] = *(const float4*)&xrow[(size_t)r * D + k4];
        }
#pragma unroll
        for (int i = 0; i < 4; i++) {
            int f = tid + i * 256;
            int r = f >> 4, k4 = (f & 15) << 2;
            float4 v = av[i];
            float hx = __bfloat162float(__float2bfloat16_rn(v.x));
            float hy = __bfloat162float(__float2bfloat16_rn(v.y));
            float hz = __bfloat162float(__float2bfloat16_rn(v.z));
            float hw = __bfloat162float(__float2bfloat16_rn(v.w));
            uint32_t d = sw128((uint32_t)(r * 128 + k4 * 2));
            *(uint2*)(smem + SO_STG + d) =
                make_uint2(pack_bf2(hx, hy), pack_bf2(hz, hw));
            *(uint2*)(smem + SO_STG + SOF_AL + d) =
                make_uint2(pack_bf2(v.x - hx, v.y - hy), pack_bf2(v.z - hz, v.w - hw));
        }
    }

    for (int c = 0; c < NCHUNK; c++) {
        const int s = c & 1;
        const uint32_t stg  = sb + SO_STG + s * STG_SZ;
        const uint32_t nstg = sb + SO_STG + (s ^ 1) * STG_SZ;

        if (c + 1 < NCHUNK) {
            // prefetch B(c+1) into other stage
#pragma unroll
            for (int i = 0; i < 8; i++) {
                int f = tid + i * 256;
                int n = f >> 3, k8 = f & 7;
                uint32_t d = sw128((uint32_t)(n * 128 + k8 * 16));
                CP_ASYNC16(nstg + SOF_BH + d, g_W1hT + n * D + (c + 1) * KCH + k8 * 8);
                CP_ASYNC16(nstg + SOF_BL + d, g_W1lT + n * D + (c + 1) * KCH + k8 * 8);
            }
            CP_COMMIT();
            // prefetch A(c+1) into regs
#pragma unroll
            for (int i = 0; i < 4; i++) {
                int f = tid + i * 256;
                int r = f >> 4, k4 = (f & 15) << 2;
                av[i] = *(const float4*)&xrow[(size_t)r * D + (c + 1) * KCH + k4];
            }
            CP_WAIT1();
        } else {
            CP_WAIT0();
        }
        __syncthreads();

        // ---- compute on stage s ----
#pragma unroll
        for (int ks = 0; ks < 4; ks++) {
            const int kb = ks * 32;   // byte offset of k-step in a 128B row
            uint32_t ah[2][4], al[2][4];
#pragma unroll
            for (int mt = 0; mt < 2; mt++) {
                int row = wm * 32 + mt * 16 + ((lane >> 3) & 1) * 8 + (lane & 7);
                int kh  = (lane >> 4) * 8;
                uint32_t off = sw128((uint32_t)(row * 128 + kb + kh * 2));
                ldsm_x4(ah[mt][0], ah[mt][1], ah[mt][2], ah[mt][3], stg + off);
                ldsm_x4(al[mt][0], al[mt][1], al[mt][2], al[mt][3], stg + SOF_AL + off);
            }
            uint32_t bh[8][2], bl[8][2];
#pragma unroll
            for (int np = 0; np < 4; np++) {
                int nrow = wn * 64 + np * 16 + (lane >> 4) * 8 + (lane & 7);
                int kh   = ((lane >> 3) & 1) * 8;
                uint32_t off = sw128((uint32_t)(nrow * 128 + kb + kh * 2));
                ldsm_x4(bh[2*np][0], bh[2*np][1], bh[2*np+1][0], bh[2*np+1][1],
                        stg + SOF_BH + off);
                ldsm_x4(bl[2*np][0], bl[2*np][1], bl[2*np+1][0], bl[2*np+1][1],
                        stg + SOF_BL + off);
            }
#pragma unroll
            for (int mt = 0; mt < 2; mt++)
#pragma unroll
                for (int nt = 0; nt < 8; nt++) mma_bf16(acc[mt][nt], ah[mt], bh[nt]);
#pragma unroll
            for (int mt = 0; mt < 2; mt++)
#pragma unroll
                for (int nt = 0; nt < 8; nt++) mma_bf16(acc[mt][nt], ah[mt], bl[nt]);
#pragma unroll
            for (int mt = 0; mt < 2; mt++)
#pragma unroll
                for (int nt = 0; nt < 8; nt++) mma_bf16(acc[mt][nt], al[mt], bh[nt]);
        }

        if (c + 1 < NCHUNK) {
            // convert + STS A(c+1) into other stage
#pragma unroll
            for (int i = 0; i < 4; i++) {
                int f = tid + i * 256;
                int r = f >> 4, k4 = (f & 15) << 2;
                float4 v = av[i];
                float hx = __bfloat162float(__float2bfloat16_rn(v.x));
                float hy = __bfloat162float(__float2bfloat16_rn(v.y));
                float hz = __bfloat162float(__float2bfloat16_rn(v.z));
                float hw = __bfloat162float(__float2bfloat16_rn(v.w));
                uint32_t d = sw128((uint32_t)(r * 128 + k4 * 2));
                *(uint2*)(smem + SO_STG + (s ^ 1) * STG_SZ + d) =
                    make_uint2(pack_bf2(hx, hy), pack_bf2(hz, hw));
                *(uint2*)(smem + SO_STG + (s ^ 1) * STG_SZ + SOF_AL + d) =
                    make_uint2(pack_bf2(v.x - hx, v.y - hy),
                               pack_bf2(v.z - hz, v.w - hw));
            }
        }
        __syncthreads();
    }

    // ---- epilogue: tanh -> x W2 partials -> cross-warp reduce ----
    const int gid = lane >> 2, tig = lane & 3;
    float* sRed4 = (float*)(smem + SO_RED);   // [wn][64][4]

#pragma unroll
    for (int mt = 0; mt < 2; mt++) {
        float p0[4] = {0, 0, 0, 0}, p1[4] = {0, 0, 0, 0};
#pragma unroll
        for (int nt = 0; nt < 8; nt++) {
            int col = wn * 64 + nt * 8 + tig * 2;
            float4 wa = W2s[col], wb = W2s[col + 1];
            float t0 = ftanh(acc[mt][nt][0]);
            float t1 = ftanh(acc[mt][nt][1]);
            float t2 = ftanh(acc[mt][nt][2]);
            float t3 = ftanh(acc[mt][nt][3]);
            p0[0] = fmaf(t0, wa.x, fmaf(t1, wb.x, p0[0]));
            p0[1] = fmaf(t0, wa.y, fmaf(t1, wb.y, p0[1]));
            p0[2] = fmaf(t0, wa.z, fmaf(t1, wb.z, p0[2]));
            p0[3] = fmaf(t0, wa.w, fmaf(t1, wb.w, p0[3]));
            p1[0] = fmaf(t2, wa.x, fmaf(t3, wb.x, p1[0]));
            p1[1] = fmaf(t2, wa.y, fmaf(t3, wb.y, p1[1]));
            p1[2] = fmaf(t2, wa.z, fmaf(t3, wb.z, p1[2]));
            p1[3] = fmaf(t2, wa.w, fmaf(t3, wb.w, p1[3]));
        }
#pragma unroll
        for (int h = 0; h < 4; h++) {
            p0[h] += __shfl_xor_sync(0xffffffffu, p0[h], 1);
            p0[h] += __shfl_xor_sync(0xffffffffu, p0[h], 2);
            p1[h] += __shfl_xor_sync(0xffffffffu, p1[h], 1);
            p1[h] += __shfl_xor_sync(0xffffffffu, p1[h], 2);
        }
        if (tig == 0) {
            int r0 = wm * 32 + mt * 16 + gid;
            int r1 = r0 + 8;
#pragma unroll
            for (int h = 0; h < 4; h++) {
                sRed4[(wn * 64 + r0) * 4 + h] = p0[h];
                sRed4[(wn * 64 + r1) * 4 + h] = p1[h];
            }
        }
    }
    __syncthreads();

    // ---- per-bag softmax (16-lane groups), head mean ----
    if (tid < MT) {
        float sc[4];
#pragma unroll
        for (int h = 0; h < 4; h++)
            sc[h] = sRed4[(0 * 64 + tid) * 4 + h] + sRed4[(1 * 64 + tid) * 4 + h]
                  + sRed4[(2 * 64 + tid) * 4 + h] + sRed4[(3 * 64 + tid) * 4 + h];
        float wsum = 0.f;
#pragma unroll
        for (int h = 0; h < 4; h++) {
            float mx = sc[h];
#pragma unroll
            for (int o = 1; o < 16; o <<= 1)
                mx = fmaxf(mx, __shfl_xor_sync(0xffffffffu, mx, o));
            float e = __expf(sc[h] - mx);
            float den = e;
#pragma unroll
            for (int o = 1; o < 16; o <<= 1)
                den += __shfl_xor_sync(0xffffffffu, den, o);
            wsum += e / den;
        }
        g_w[rowBase + tid] = 0.25f * wsum;
    }
}

// ---------------------------------------------------------------------------
// bag kernel: bag_repr = sum_r w_r x_r ; logits = bag_repr @ Wc^T + bc
// ---------------------------------------------------------------------------
__global__ __launch_bounds__(256) void bag_kernel(
    const float* __restrict__ x,
    const float* __restrict__ bc,
    float* __restrict__ out)
{
    __shared__ float rep[D];
    __shared__ float ws[BAG];

    const int b = blockIdx.x;
    const int tid = threadIdx.x;

    if (tid < BAG) ws[tid] = g_w[b * BAG + tid];
    __syncthreads();

    const float* xb = x + (size_t)b * BAG * D;
    float r0 = 0.0f, r1 = 0.0f;
#pragma unroll
    for (int r = 0; r < BAG; r++) {
        float w = ws[r];
        r0 = fmaf(w, xb[r * D + tid],       r0);
        r1 = fmaf(w, xb[r * D + tid + 256], r1);
    }
    rep[tid]       = r0;
    rep[tid + 256] = r1;
    __syncthreads();

    const int warp = tid >> 5;
    const int lane = tid & 31;
    for (int c = warp; c < NC; c += 8) {
        const float* wc = &g_WcT[c * D];
        float s = 0.0f;
#pragma unroll
        for (int q = 0; q < 4; q++) {
            int d4 = lane + q * 32;
            float4 rv = *(const float4*)&rep[d4 * 4];
            float4 wv = *(const float4*)&wc[d4 * 4];
            s = fmaf(rv.x, wv.x, s);
            s = fmaf(rv.y, wv.y, s);
            s = fmaf(rv.z, wv.z, s);
            s = fmaf(rv.w, wv.w, s);
        }
        s += __shfl_xor_sync(0xffffffffu, s, 16);
        s += __shfl_xor_sync(0xffffffffu, s, 8);
        s += __shfl_xor_sync(0xffffffffu, s, 4);
        s += __shfl_xor_sync(0xffffffffu, s, 2);
        s += __shfl_xor_sync(0xffffffffu, s, 1);
        if (lane == 0) out[b * NC + c] = s + bc[c];
    }
}

// ---------------------------------------------------------------------------
extern "C" void kernel_launch(void* const* d_in, const int* in_sizes, int n_in,
                              void* d_out, int out_size)
{
    const float* x  = (const float*)d_in[0];
    const float* W1 = (const float*)d_in[1];
    const float* W2 = (const float*)d_in[2];
    const float* Wc = (const float*)d_in[3];
    const float* bc = (const float*)d_in[4];
    float* out = (float*)d_out;

    cudaFuncSetAttribute(scores_mma_kernel,
                         cudaFuncAttributeMaxDynamicSharedMemorySize, SMEM_SZ);

    convert_w1_kernel<<<(D * DA + 255) / 256, 256>>>(W1);
    transpose_wc_kernel<<<(D * NC + 255) / 256, 256>>>(Wc);
    scores_mma_kernel<<<N_TOT / MT, 256, SMEM_SZ>>>(x, W2);
    bag_kernel<<<NBAGS, 256>>>(x, bc, out);
}

// round 10
// speedup vs baseline: 2.6123x; 1.1625x over previous
#include <cuda_runtime.h>
#include <cuda_fp16.h>
#include <cstdint>
#include <math.h>

#define N_TOT   131072
#define D       512
#define DA      256
#define NH      4
#define NC      53
#define BAG     16
#define NBAGS   8192

#define MT      64          // CTA rows (4 bags)
#define KCH     64          // K chunk
#define NCHUNK  (D / KCH)   // 8

// ---------------------------------------------------------------------------
// device scratch (allocation is forbidden)
// ---------------------------------------------------------------------------
__device__ float g_w[N_TOT];
__device__ float g_WcT[NC * D];
__device__ __align__(256) __half g_W1hH[DA * D];   // (n, k) k-contig, W1 hi
__device__ __align__(256) __half g_W1lH[DA * D];   // W1 lo  (w - wh)

// ---------------------------------------------------------------------------
// helpers
// ---------------------------------------------------------------------------
__device__ __forceinline__ uint32_t smem_u32(const void* p) {
    uint32_t a;
    asm("{ .reg .u64 t; cvta.to.shared.u64 t, %1; cvt.u32.u64 %0, t; }" : "=r"(a) : "l"(p));
    return a;
}
__device__ __forceinline__ uint32_t sw128(uint32_t o) { return o ^ ((o >> 3) & 0x70); }

#define CP_ASYNC16(dst, src) \
    asm volatile("cp.async.cg.shared.global [%0], [%1], 16;" :: "r"(dst), "l"(src) : "memory")
#define CP_COMMIT() asm volatile("cp.async.commit_group;" ::: "memory")
#define CP_WAIT1()  asm volatile("cp.async.wait_group 1;" ::: "memory")
#define CP_WAIT0()  asm volatile("cp.async.wait_group 0;" ::: "memory")

__device__ __forceinline__ void ldsm_x4(uint32_t& r0, uint32_t& r1, uint32_t& r2,
                                        uint32_t& r3, uint32_t addr) {
    asm volatile("ldmatrix.sync.aligned.m8n8.x4.shared.b16 {%0,%1,%2,%3}, [%4];"
                 : "=r"(r0), "=r"(r1), "=r"(r2), "=r"(r3) : "r"(addr));
}

__device__ __forceinline__ void mma_f16(float* d, const uint32_t* a, const uint32_t* b) {
    asm volatile("mma.sync.aligned.m16n8k16.row.col.f32.f16.f16.f32 "
                 "{%0,%1,%2,%3}, {%4,%5,%6,%7}, {%8,%9}, {%0,%1,%2,%3};"
                 : "+f"(d[0]), "+f"(d[1]), "+f"(d[2]), "+f"(d[3])
                 : "r"(a[0]), "r"(a[1]), "r"(a[2]), "r"(a[3]), "r"(b[0]), "r"(b[1]));
}

__device__ __forceinline__ float ftanh(float v) {
    float e2 = __expf(2.0f * v);
    return 1.0f - __fdividef(2.0f, e2 + 1.0f);
}
__device__ __forceinline__ uint32_t pack_h2(float a, float b) {
    __half2 h = __floats2half2_rn(a, b);
    return *reinterpret_cast<uint32_t*>(&h);
}

// ---------------------------------------------------------------------------
// prep kernels
// ---------------------------------------------------------------------------
__global__ void transpose_wc_kernel(const float* __restrict__ Wc) {
    int i = blockIdx.x * blockDim.x + threadIdx.x;
    if (i < D * NC) {
        int d = i / NC, c = i - d * NC;
        g_WcT[c * D + d] = Wc[i];
    }
}
__global__ void convert_w1_kernel(const float* __restrict__ W1) {
    int i = blockIdx.x * blockDim.x + threadIdx.x;   // over D*DA, (k, n) in
    if (i < D * DA) {
        int k = i >> 8, n = i & 255;
        float v = W1[i];
        __half h = __float2half_rn(v);
        float lo = v - __half2float(h);
        g_W1hH[n * D + k] = h;
        g_W1lH[n * D + k] = __float2half_rn(lo);
    }
}

// ---------------------------------------------------------------------------
// scores kernel: fp16 2-term split GEMM (64x256xK) + tanh/W2 + bag softmax
// smem: [0,4K) W2; [4K,8K) sRed4; stages at 8K, per stage (72K):
//   A 8K | Bhi 32K | Blo 32K
// ---------------------------------------------------------------------------
#define SO_W2    0
#define SO_RED   4096
#define SO_STG   8192
#define STG_SZ   73728
#define SOF_BH   8192
#define SOF_BL   40960
#define SMEM_SZ  (SO_STG + 2 * STG_SZ)   // 155648

__global__ void __launch_bounds__(256, 1) scores_mma_kernel(
    const float* __restrict__ x,
    const float* __restrict__ W2)
{
    extern __shared__ char smem[];
    const uint32_t sb = smem_u32(smem);
    const int tid  = threadIdx.x;
    const int warp = tid >> 5;
    const int lane = tid & 31;
    const int wm = warp & 1;        // 0..1 : 32-row group
    const int wn = warp >> 1;       // 0..3 : 64-col group
    const size_t rowBase = (size_t)blockIdx.x * MT;
    const float* xrow = x + rowBase * D;

    float4* W2s = (float4*)(smem + SO_W2);
    for (int i = tid; i < DA; i += 256) W2s[i] = ((const float4*)W2)[i];

    float acc[2][8][4];
#pragma unroll
    for (int mt = 0; mt < 2; mt++)
#pragma unroll
        for (int nt = 0; nt < 8; nt++)
#pragma unroll
            for (int q = 0; q < 4; q++) acc[mt][nt][q] = 0.0f;

    float4 av[4];

    // prologue: B0 cp.async, A0 ldg+convert+STS
    {
#pragma unroll
        for (int i = 0; i < 8; i++) {
            int f = tid + i * 256;
            int n = f >> 3, k8 = f & 7;
            uint32_t d = sw128((uint32_t)(n * 128 + k8 * 16));
            CP_ASYNC16(sb + SO_STG + SOF_BH + d, g_W1hH + n * D + k8 * 8);
            CP_ASYNC16(sb + SO_STG + SOF_BL + d, g_W1lH + n * D + k8 * 8);
        }
        CP_COMMIT();
#pragma unroll
        for (int i = 0; i < 4; i++) {
            int f = tid + i * 256;
            int r = f >> 4, k4 = (f & 15) << 2;
            av[i] = *(const float4*)&xrow[(size_t)r * D + k4];
        }
#pragma unroll
        for (int i = 0; i < 4; i++) {
            int f = tid + i * 256;
            int r = f >> 4, k4 = (f & 15) << 2;
            float4 v = av[i];
            uint32_t d = sw128((uint32_t)(r * 128 + k4 * 2));
            *(uint2*)(smem + SO_STG + d) =
                make_uint2(pack_h2(v.x, v.y), pack_h2(v.z, v.w));
        }
    }

    for (int c = 0; c < NCHUNK; c++) {
        const int s = c & 1;
        const uint32_t stg  = sb + SO_STG + s * STG_SZ;
        const uint32_t nstg = sb + SO_STG + (s ^ 1) * STG_SZ;

        if (c + 1 < NCHUNK) {
#pragma unroll
            for (int i = 0; i < 8; i++) {
                int f = tid + i * 256;
                int n = f >> 3, k8 = f & 7;
                uint32_t d = sw128((uint32_t)(n * 128 + k8 * 16));
                CP_ASYNC16(nstg + SOF_BH + d, g_W1hH + n * D + (c + 1) * KCH + k8 * 8);
                CP_ASYNC16(nstg + SOF_BL + d, g_W1lH + n * D + (c + 1) * KCH + k8 * 8);
            }
            CP_COMMIT();
#pragma unroll
            for (int i = 0; i < 4; i++) {
                int f = tid + i * 256;
                int r = f >> 4, k4 = (f & 15) << 2;
                av[i] = *(const float4*)&xrow[(size_t)r * D + (c + 1) * KCH + k4];
            }
            CP_WAIT1();
        } else {
            CP_WAIT0();
        }
        __syncthreads();

        // ---- compute on stage s ----
#pragma unroll
        for (int ks = 0; ks < 4; ks++) {
            const int kb = ks * 32;
            uint32_t ah[2][4];
#pragma unroll
            for (int mt = 0; mt < 2; mt++) {
                int row = wm * 32 + mt * 16 + ((lane >> 3) & 1) * 8 + (lane & 7);
                int kh  = (lane >> 4) * 8;
                uint32_t off = sw128((uint32_t)(row * 128 + kb + kh * 2));
                ldsm_x4(ah[mt][0], ah[mt][1], ah[mt][2], ah[mt][3], stg + off);
            }
            uint32_t bh[8][2], bl[8][2];
#pragma unroll
            for (int np = 0; np < 4; np++) {
                int nrow = wn * 64 + np * 16 + (lane >> 4) * 8 + (lane & 7);
                int kh   = ((lane >> 3) & 1) * 8;
                uint32_t off = sw128((uint32_t)(nrow * 128 + kb + kh * 2));
                ldsm_x4(bh[2*np][0], bh[2*np][1], bh[2*np+1][0], bh[2*np+1][1],
                        stg + SOF_BH + off);
                ldsm_x4(bl[2*np][0], bl[2*np][1], bl[2*np+1][0], bl[2*np+1][1],
                        stg + SOF_BL + off);
            }
#pragma unroll
            for (int mt = 0; mt < 2; mt++)
#pragma unroll
                for (int nt = 0; nt < 8; nt++) mma_f16(acc[mt][nt], ah[mt], bh[nt]);
#pragma unroll
            for (int mt = 0; mt < 2; mt++)
#pragma unroll
                for (int nt = 0; nt < 8; nt++) mma_f16(acc[mt][nt], ah[mt], bl[nt]);
        }

        if (c + 1 < NCHUNK) {
#pragma unroll
            for (int i = 0; i < 4; i++) {
                int f = tid + i * 256;
                int r = f >> 4, k4 = (f & 15) << 2;
                float4 v = av[i];
                uint32_t d = sw128((uint32_t)(r * 128 + k4 * 2));
                *(uint2*)(smem + SO_STG + (s ^ 1) * STG_SZ + d) =
                    make_uint2(pack_h2(v.x, v.y), pack_h2(v.z, v.w));
            }
        }
        __syncthreads();
    }

    // ---- epilogue: tanh -> x W2 partials -> cross-warp reduce ----
    const int gid = lane >> 2, tig = lane & 3;
    float* sRed4 = (float*)(smem + SO_RED);   // [wn][64][4]

#pragma unroll
    for (int mt = 0; mt < 2; mt++) {
        float p0[4] = {0, 0, 0, 0}, p1[4] = {0, 0, 0, 0};
#pragma unroll
        for (int nt = 0; nt < 8; nt++) {
            int col = wn * 64 + nt * 8 + tig * 2;
            float4 wa = W2s[col], wb = W2s[col + 1];
            float t0 = ftanh(acc[mt][nt][0]);
            float t1 = ftanh(acc[mt][nt][1]);
            float t2 = ftanh(acc[mt][nt][2]);
            float t3 = ftanh(acc[mt][nt][3]);
            p0[0] = fmaf(t0, wa.x, fmaf(t1, wb.x, p0[0]));
            p0[1] = fmaf(t0, wa.y, fmaf(t1, wb.y, p0[1]));
            p0[2] = fmaf(t0, wa.z, fmaf(t1, wb.z, p0[2]));
            p0[3] = fmaf(t0, wa.w, fmaf(t1, wb.w, p0[3]));
            p1[0] = fmaf(t2, wa.x, fmaf(t3, wb.x, p1[0]));
            p1[1] = fmaf(t2, wa.y, fmaf(t3, wb.y, p1[1]));
            p1[2] = fmaf(t2, wa.z, fmaf(t3, wb.z, p1[2]));
            p1[3] = fmaf(t2, wa.w, fmaf(t3, wb.w, p1[3]));
        }
#pragma unroll
        for (int h = 0; h < 4; h++) {
            p0[h] += __shfl_xor_sync(0xffffffffu, p0[h], 1);
            p0[h] += __shfl_xor_sync(0xffffffffu, p0[h], 2);
            p1[h] += __shfl_xor_sync(0xffffffffu, p1[h], 1);
            p1[h] += __shfl_xor_sync(0xffffffffu, p1[h], 2);
        }
        if (tig == 0) {
            int r0 = wm * 32 + mt * 16 + gid;
            int r1 = r0 + 8;
#pragma unroll
            for (int h = 0; h < 4; h++) {
                sRed4[(wn * 64 + r0) * 4 + h] = p0[h];
                sRed4[(wn * 64 + r1) * 4 + h] = p1[h];
            }
        }
    }
    __syncthreads();

    // ---- per-bag softmax (16-lane groups), head mean ----
    if (tid < MT) {
        float sc[4];
#pragma unroll
        for (int h = 0; h < 4; h++)
            sc[h] = sRed4[(0 * 64 + tid) * 4 + h] + sRed4[(1 * 64 + tid) * 4 + h]
                  + sRed4[(2 * 64 + tid) * 4 + h] + sRed4[(3 * 64 + tid) * 4 + h];
        float wsum = 0.f;
#pragma unroll
        for (int h = 0; h < 4; h++) {
            float mx = sc[h];
#pragma unroll
            for (int o = 1; o < 16; o <<= 1)
                mx = fmaxf(mx, __shfl_xor_sync(0xffffffffu, mx, o));
            float e = __expf(sc[h] - mx);
            float den = e;
#pragma unroll
            for (int o = 1; o < 16; o <<= 1)
                den += __shfl_xor_sync(0xffffffffu, den, o);
            wsum += e / den;
        }
        g_w[rowBase + tid] = 0.25f * wsum;
    }
}

// ---------------------------------------------------------------------------
// bag kernel v2: 2 bags/block, float4 columns, 16 independent LDG.128
// ---------------------------------------------------------------------------
__global__ __launch_bounds__(256) void bag_kernel(
    const float* __restrict__ x,
    const float* __restrict__ bc,
    float* __restrict__ out)
{
    __shared__ float4 rep4[2][128];
    __shared__ float ws[2][BAG];

    const int tid = threadIdx.x;
    const int b0  = blockIdx.x * 2;

    if (tid < 32) ws[tid >> 4][tid & 15] = g_w[(size_t)b0 * BAG + tid];
    __syncthreads();

    const int half = tid >> 7;
    const int t    = tid & 127;
    const float4* xb = (const float4*)(x + (size_t)(b0 + half) * BAG * D);

    float4 a = make_float4(0.f, 0.f, 0.f, 0.f);
#pragma unroll
    for (int r = 0; r < BAG; r++) {
        float w = ws[half][r];
        float4 v = xb[r * 128 + t];
        a.x = fmaf(w, v.x, a.x);
        a.y = fmaf(w, v.y, a.y);
        a.z = fmaf(w, v.z, a.z);
        a.w = fmaf(w, v.w, a.w);
    }
    rep4[half][t] = a;
    __syncthreads();

    const int warp = tid >> 5;
    const int lane = tid & 31;
    for (int p = warp; p < 2 * NC; p += 8) {
        const int bb = (p >= NC) ? 1 : 0;
        const int c  = p - bb * NC;
        const float4* wc = (const float4*)&g_WcT[c * D];
        const float4* rp = &rep4[bb][0];
        float s = 0.0f;
#pragma unroll
        for (int q = 0; q < 4; q++) {
            int i = lane + q * 32;
            float4 rv = rp[i];
            float4 wv = wc[i];
            s = fmaf(rv.x, wv.x, s);
            s = fmaf(rv.y, wv.y, s);
            s = fmaf(rv.z, wv.z, s);
            s = fmaf(rv.w, wv.w, s);
        }
        s += __shfl_xor_sync(0xffffffffu, s, 16);
        s += __shfl_xor_sync(0xffffffffu, s, 8);
        s += __shfl_xor_sync(0xffffffffu, s, 4);
        s += __shfl_xor_sync(0xffffffffu, s, 2);
        s += __shfl_xor_sync(0xffffffffu, s, 1);
        if (lane == 0) out[(b0 + bb) * NC + c] = s + bc[c];
    }
}

// ---------------------------------------------------------------------------
extern "C" void kernel_launch(void* const* d_in, const int* in_sizes, int n_in,
                              void* d_out, int out_size)
{
    const float* x  = (const float*)d_in[0];
    const float* W1 = (const float*)d_in[1];
    const float* W2 = (const float*)d_in[2];
    const float* Wc = (const float*)d_in[3];
    const float* bc = (const float*)d_in[4];
    float* out = (float*)d_out;

    cudaFuncSetAttribute(scores_mma_kernel,
                         cudaFuncAttributeMaxDynamicSharedMemorySize, SMEM_SZ);

    convert_w1_kernel<<<(D * DA + 255) / 256, 256>>>(W1);
    transpose_wc_kernel<<<(D * NC + 255) / 256, 256>>>(Wc);
    scores_mma_kernel<<<N_TOT / MT, 256, SMEM_SZ>>>(x, W2);
    bag_kernel<<<NBAGS / 2, 256>>>(x, bc, out);
}

// round 11
// speedup vs baseline: 3.2731x; 1.2530x over previous
#include <cuda_runtime.h>
#include <cuda_fp16.h>
#include <cstdint>
#include <math.h>

#define N_TOT   131072
#define D       512
#define DA      256
#define NH      4
#define NC      53
#define BAG     16
#define NBAGS   8192

#define MT      64          // CTA rows (4 bags)
#define KCH     64          // K chunk (128 bytes fp16)
#define NCHUNK  (D / KCH)   // 8

// ---------------------------------------------------------------------------
// device scratch (allocation is forbidden)
// ---------------------------------------------------------------------------
__device__ float g_WcT[NC * D];
__device__ __align__(256) __half g_W1hH[DA * D];   // W1^T fp16, (n, k) k-contig

// ---------------------------------------------------------------------------
// helpers
// ---------------------------------------------------------------------------
__device__ __forceinline__ uint32_t smem_u32(const void* p) {
    uint32_t a;
    asm("{ .reg .u64 t; cvta.to.shared.u64 t, %1; cvt.u32.u64 %0, t; }" : "=r"(a) : "l"(p));
    return a;
}
__device__ __forceinline__ uint32_t sw128(uint32_t o) { return o ^ ((o >> 3) & 0x70); }

#define CP_ASYNC16(dst, src) \
    asm volatile("cp.async.cg.shared.global [%0], [%1], 16;" :: "r"(dst), "l"(src) : "memory")
#define CP_COMMIT() asm volatile("cp.async.commit_group;" ::: "memory")
#define CP_WAIT0()  asm volatile("cp.async.wait_group 0;" ::: "memory")

__device__ __forceinline__ void ldsm_x4(uint32_t& r0, uint32_t& r1, uint32_t& r2,
                                        uint32_t& r3, uint32_t addr) {
    asm volatile("ldmatrix.sync.aligned.m8n8.x4.shared.b16 {%0,%1,%2,%3}, [%4];"
                 : "=r"(r0), "=r"(r1), "=r"(r2), "=r"(r3) : "r"(addr));
}
__device__ __forceinline__ void mma_f16(float* d, const uint32_t* a, const uint32_t* b) {
    asm volatile("mma.sync.aligned.m16n8k16.row.col.f32.f16.f16.f32 "
                 "{%0,%1,%2,%3}, {%4,%5,%6,%7}, {%8,%9}, {%0,%1,%2,%3};"
                 : "+f"(d[0]), "+f"(d[1]), "+f"(d[2]), "+f"(d[3])
                 : "r"(a[0]), "r"(a[1]), "r"(a[2]), "r"(a[3]), "r"(b[0]), "r"(b[1]));
}
__device__ __forceinline__ float ftanh(float v) {
    float e2 = __expf(2.0f * v);
    return 1.0f - __fdividef(2.0f, e2 + 1.0f);
}
__device__ __forceinline__ uint32_t pack_h2(float a, float b) {
    __half2 h = __floats2half2_rn(a, b);
    return *reinterpret_cast<uint32_t*>(&h);
}

// ---------------------------------------------------------------------------
// prep kernels
// ---------------------------------------------------------------------------
__global__ void transpose_wc_kernel(const float* __restrict__ Wc) {
    int i = blockIdx.x * blockDim.x + threadIdx.x;
    if (i < D * NC) {
        int d = i / NC, c = i - d * NC;
        g_WcT[c * D + d] = Wc[i];
    }
}
__global__ void convert_w1_kernel(const float* __restrict__ W1) {
    int i = blockIdx.x * blockDim.x + threadIdx.x;   // over D*DA, (k, n) in
    if (i < D * DA) {
        int k = i >> 8, n = i & 255;
        g_W1hH[n * D + k] = __float2half_rn(W1[i]);
    }
}

// ---------------------------------------------------------------------------
// fused kernel: fp16 GEMM (64x256x512) + tanh/W2 + bag softmax
//               + bag weighted-sum (from resident fp16 A) + classifier
// smem layout (bytes):
//   0      W2s      4096   (float4[256])
//   4096   sRed4    4096   ([4][64][4] float)
//   8192   sw       256    (w[64])
//   8704   A        65536  (8 sub-tiles, each 64 rows x 128B, sw128)
//   74240  B        32768  (256 n-rows x 128B, sw128)  -- reused as rep[4][512] f32
// ---------------------------------------------------------------------------
#define SO_W2    0
#define SO_RED   4096
#define SO_SW    8192
#define SOF_A    8704
#define SOF_B    74240
#define SO_REP   SOF_B
#define SMEM_SZ  (SOF_B + 32768)   // 107008

__global__ void __launch_bounds__(256, 2) fused_kernel(
    const float* __restrict__ x,
    const float* __restrict__ W2,
    const float* __restrict__ bc,
    float* __restrict__ out)
{
    extern __shared__ char smem[];
    const uint32_t sb = smem_u32(smem);
    const int tid  = threadIdx.x;
    const int warp = tid >> 5;
    const int lane = tid & 31;
    const int wm = warp & 1;        // 0..1 : 32-row group
    const int wn = warp >> 1;       // 0..3 : 64-col group
    const size_t rowBase = (size_t)blockIdx.x * MT;
    const float* xrow = x + rowBase * D;

    float4* W2s = (float4*)(smem + SO_W2);
    for (int i = tid; i < DA; i += 256) W2s[i] = ((const float4*)W2)[i];

    // ---- prologue: B chunk 0 via cp.async; full A tile ldg+convert+STS ----
#pragma unroll
    for (int i = 0; i < 8; i++) {
        int f = tid + i * 256;
        int n = f >> 3, k8 = f & 7;
        CP_ASYNC16(sb + SOF_B + sw128((uint32_t)(n * 128 + k8 * 16)),
                   g_W1hH + n * D + k8 * 8);
    }
    CP_COMMIT();

#pragma unroll
    for (int i = 0; i < 32; i++) {
        int f  = tid + i * 256;          // float4 idx over 8192
        int r  = f >> 7;                 // 128 float4 per row
        int k4 = (f & 127) << 2;         // float index within row
        float4 v = *(const float4*)&xrow[(size_t)r * D + k4];
        int chunk = k4 >> 6;
        int inner = (k4 & 63) << 1;      // byte offset in 128B row
        *(uint2*)(smem + SOF_A + chunk * 8192 + sw128((uint32_t)(r * 128 + inner))) =
            make_uint2(pack_h2(v.x, v.y), pack_h2(v.z, v.w));
    }

    float acc[2][8][4];
#pragma unroll
    for (int mt = 0; mt < 2; mt++)
#pragma unroll
        for (int nt = 0; nt < 8; nt++)
#pragma unroll
            for (int q = 0; q < 4; q++) acc[mt][nt][q] = 0.0f;

    // ---- main loop over 8 K chunks, single-buffered B ----
    for (int c = 0; c < NCHUNK; c++) {
        CP_WAIT0();
        __syncthreads();

        const uint32_t stgA = sb + SOF_A + c * 8192;
        const uint32_t stgB = sb + SOF_B;

#pragma unroll
        for (int ks = 0; ks < 4; ks++) {
            const int kb = ks * 32;
            uint32_t ah[2][4];
#pragma unroll
            for (int mt = 0; mt < 2; mt++) {
                int row = wm * 32 + mt * 16 + ((lane >> 3) & 1) * 8 + (lane & 7);
                int kh  = (lane >> 4) * 8;
                ldsm_x4(ah[mt][0], ah[mt][1], ah[mt][2], ah[mt][3],
                        stgA + sw128((uint32_t)(row * 128 + kb + kh * 2)));
            }
            uint32_t bh[8][2];
#pragma unroll
            for (int np = 0; np < 4; np++) {
                int nrow = wn * 64 + np * 16 + (lane >> 4) * 8 + (lane & 7);
                int kh   = ((lane >> 3) & 1) * 8;
                ldsm_x4(bh[2*np][0], bh[2*np][1], bh[2*np+1][0], bh[2*np+1][1],
                        stgB + sw128((uint32_t)(nrow * 128 + kb + kh * 2)));
            }
#pragma unroll
            for (int mt = 0; mt < 2; mt++)
#pragma unroll
                for (int nt = 0; nt < 8; nt++) mma_f16(acc[mt][nt], ah[mt], bh[nt]);
        }
        __syncthreads();

        if (c + 1 < NCHUNK) {
#pragma unroll
            for (int i = 0; i < 8; i++) {
                int f = tid + i * 256;
                int n = f >> 3, k8 = f & 7;
                CP_ASYNC16(sb + SOF_B + sw128((uint32_t)(n * 128 + k8 * 16)),
                           g_W1hH + n * D + (c + 1) * KCH + k8 * 8);
            }
            CP_COMMIT();
        }
    }

    // ---- epilogue 1: tanh -> x W2 partials -> cross-warp reduce ----
    const int gid = lane >> 2, tig = lane & 3;
    float* sRed4 = (float*)(smem + SO_RED);   // [wn][64][4]

#pragma unroll
    for (int mt = 0; mt < 2; mt++) {
        float p0[4] = {0, 0, 0, 0}, p1[4] = {0, 0, 0, 0};
#pragma unroll
        for (int nt = 0; nt < 8; nt++) {
            int col = wn * 64 + nt * 8 + tig * 2;
            float4 wa = W2s[col], wb = W2s[col + 1];
            float t0 = ftanh(acc[mt][nt][0]);
            float t1 = ftanh(acc[mt][nt][1]);
            float t2 = ftanh(acc[mt][nt][2]);
            float t3 = ftanh(acc[mt][nt][3]);
            p0[0] = fmaf(t0, wa.x, fmaf(t1, wb.x, p0[0]));
            p0[1] = fmaf(t0, wa.y, fmaf(t1, wb.y, p0[1]));
            p0[2] = fmaf(t0, wa.z, fmaf(t1, wb.z, p0[2]));
            p0[3] = fmaf(t0, wa.w, fmaf(t1, wb.w, p0[3]));
            p1[0] = fmaf(t2, wa.x, fmaf(t3, wb.x, p1[0]));
            p1[1] = fmaf(t2, wa.y, fmaf(t3, wb.y, p1[1]));
            p1[2] = fmaf(t2, wa.z, fmaf(t3, wb.z, p1[2]));
            p1[3] = fmaf(t2, wa.w, fmaf(t3, wb.w, p1[3]));
        }
#pragma unroll
        for (int h = 0; h < 4; h++) {
            p0[h] += __shfl_xor_sync(0xffffffffu, p0[h], 1);
            p0[h] += __shfl_xor_sync(0xffffffffu, p0[h], 2);
            p1[h] += __shfl_xor_sync(0xffffffffu, p1[h], 1);
            p1[h] += __shfl_xor_sync(0xffffffffu, p1[h], 2);
        }
        if (tig == 0) {
            int r0 = wm * 32 + mt * 16 + gid;
            int r1 = r0 + 8;
#pragma unroll
            for (int h = 0; h < 4; h++) {
                sRed4[(wn * 64 + r0) * 4 + h] = p0[h];
                sRed4[(wn * 64 + r1) * 4 + h] = p1[h];
            }
        }
    }
    __syncthreads();

    // ---- epilogue 2: per-bag softmax (16-lane groups), head-mean weight ----
    float* sw = (float*)(smem + SO_SW);
    if (tid < MT) {
        float sc[4];
#pragma unroll
        for (int h = 0; h < 4; h++)
            sc[h] = sRed4[(0 * 64 + tid) * 4 + h] + sRed4[(1 * 64 + tid) * 4 + h]
                  + sRed4[(2 * 64 + tid) * 4 + h] + sRed4[(3 * 64 + tid) * 4 + h];
        float wsum = 0.f;
#pragma unroll
        for (int h = 0; h < 4; h++) {
            float mx = sc[h];
#pragma unroll
            for (int o = 1; o < 16; o <<= 1)
                mx = fmaxf(mx, __shfl_xor_sync(0xffffffffu, mx, o));
            float e = __expf(sc[h] - mx);
            float den = e;
#pragma unroll
            for (int o = 1; o < 16; o <<= 1)
                den += __shfl_xor_sync(0xffffffffu, den, o);
            wsum += e / den;
        }
        sw[tid] = 0.25f * wsum;
    }
    __syncthreads();

    // ---- epilogue 3: bag weighted sums from resident fp16 A ----
    // thread -> (bag = tid>>6, 8 cols = (tid&63)*8)
    {
        const int bag = tid >> 6;
        const int cg  = tid & 63;
        const int chunk = cg >> 3;            // 8 col-groups per chunk
        const int innerb = (cg & 7) * 16;     // byte offset of 8 fp16
        const uint32_t abase = sb + SOF_A + chunk * 8192;

        float a8[8];
#pragma unroll
        for (int j = 0; j < 8; j++) a8[j] = 0.f;
#pragma unroll
        for (int r = 0; r < BAG; r++) {
            int row = bag * BAG + r;
            float w = sw[row];
            uint4 v;
            asm volatile("ld.shared.v4.u32 {%0,%1,%2,%3}, [%4];"
                         : "=r"(v.x), "=r"(v.y), "=r"(v.z), "=r"(v.w)
                         : "r"(abase + sw128((uint32_t)(row * 128 + innerb))));
            const __half2* h2 = (const __half2*)&v;
#pragma unroll
            for (int q = 0; q < 4; q++) {
                float2 f2 = __half22float2(h2[q]);
                a8[2*q]   = fmaf(w, f2.x, a8[2*q]);
                a8[2*q+1] = fmaf(w, f2.y, a8[2*q+1]);
            }
        }
        __syncthreads();   // done reading A/B regions; rep aliases B
        float* rep = (float*)(smem + SO_REP);
        int base = bag * D + cg * 8;
#pragma unroll
        for (int j = 0; j < 8; j++) rep[base + j] = a8[j];
    }
    __syncthreads();

    // ---- epilogue 4: classifier  logits = rep @ WcT + bc ----
    {
        const float4* rep4 = (const float4*)(smem + SO_REP);
        for (int p = warp; p < 4 * NC; p += 8) {
            const int bag = p / NC;
            const int c   = p - bag * NC;
            const float4* wc = (const float4*)&g_WcT[c * D];
            const float4* rp = &rep4[bag * 128];
            float s = 0.0f;
#pragma unroll
            for (int q = 0; q < 4; q++) {
                int i = lane + q * 32;
                float4 rv = rp[i];
                float4 wv = wc[i];
                s = fmaf(rv.x, wv.x, s);
                s = fmaf(rv.y, wv.y, s);
                s = fmaf(rv.z, wv.z, s);
                s = fmaf(rv.w, wv.w, s);
            }
            s += __shfl_xor_sync(0xffffffffu, s, 16);
            s += __shfl_xor_sync(0xffffffffu, s, 8);
            s += __shfl_xor_sync(0xffffffffu, s, 4);
            s += __shfl_xor_sync(0xffffffffu, s, 2);
            s += __shfl_xor_sync(0xffffffffu, s, 1);
            if (lane == 0)
                out[((size_t)blockIdx.x * 4 + bag) * NC + c] = s + bc[c];
        }
    }
}

// ---------------------------------------------------------------------------
extern "C" void kernel_launch(void* const* d_in, const int* in_sizes, int n_in,
                              void* d_out, int out_size)
{
    const float* x  = (const float*)d_in[0];
    const float* W1 = (const float*)d_in[1];
    const float* W2 = (const float*)d_in[2];
    const float* Wc = (const float*)d_in[3];
    const float* bc = (const float*)d_in[4];
    float* out = (float*)d_out;

    cudaFuncSetAttribute(fused_kernel,
                         cudaFuncAttributeMaxDynamicSharedMemorySize, SMEM_SZ);

    convert_w1_kernel<<<(D * DA + 255) / 256, 256>>>(W1);
    transpose_wc_kernel<<<(D * NC + 255) / 256, 256>>>(Wc);
    fused_kernel<<<N_TOT / MT, 256, SMEM_SZ>>>(x, W2, bc, out);
}